// round 10
// baseline (speedup 1.0000x reference)
#include <cuda_runtime.h>
#include <cuda_bf16.h>
#include <cuda_fp16.h>
#include <cstdint>
#include <cstring>

namespace {

constexpr int B_ = 2, L_ = 2048, S_ = 2048, H_ = 8, E_ = 64;
constexpr int BQ = 64, BK = 64, NTH = 128;
constexpr int NIT = L_ / BQ;   // 32 query tiles
constexpr int NJT = S_ / BK;   // 32 key tiles
constexpr float SCALE = 0.125f;  // 1/sqrt(64)
constexpr long long V_SZ = (long long)B_ * L_ * H_ * E_;
constexpr long long A_SZ = (long long)B_ * H_ * L_ * S_;
constexpr long long NEL = (long long)B_ * H_ * 2048 * E_;  // 2,097,152

// ---- persistent scratch (device globals; no runtime allocation) ----------
__device__ __nv_bfloat16 gQh[NEL], gQl[NEL];   // [b,h,l,e]
__device__ __nv_bfloat16 gKh[NEL], gKl[NEL];   // [b,h,s,e]
__device__ __half gVt[NEL];                    // [b,h,e,s]
__device__ unsigned long long g_mkbits[B_ * NJT];
__device__ float g_invZ[B_ * H_ * L_];

// ---- PTX helpers ---------------------------------------------------------
__device__ __forceinline__ void mma16816(float* c, const uint32_t* a,
                                         uint32_t b0, uint32_t b1) {
  asm volatile(
      "mma.sync.aligned.m16n8k16.row.col.f32.bf16.bf16.f32 "
      "{%0,%1,%2,%3}, {%4,%5,%6,%7}, {%8,%9}, {%0,%1,%2,%3};\n"
      : "+f"(c[0]), "+f"(c[1]), "+f"(c[2]), "+f"(c[3])
      : "r"(a[0]), "r"(a[1]), "r"(a[2]), "r"(a[3]), "r"(b0), "r"(b1));
}

__device__ __forceinline__ void mma16816f(float* c, const uint32_t* a,
                                          uint32_t b0, uint32_t b1) {
  asm volatile(
      "mma.sync.aligned.m16n8k16.row.col.f32.f16.f16.f32 "
      "{%0,%1,%2,%3}, {%4,%5,%6,%7}, {%8,%9}, {%0,%1,%2,%3};\n"
      : "+f"(c[0]), "+f"(c[1]), "+f"(c[2]), "+f"(c[3])
      : "r"(a[0]), "r"(a[1]), "r"(a[2]), "r"(a[3]), "r"(b0), "r"(b1));
}

__device__ __forceinline__ void ldsm4(uint32_t* r, uint32_t addr) {
  asm volatile(
      "ldmatrix.sync.aligned.m8n8.x4.shared.b16 {%0,%1,%2,%3}, [%4];\n"
      : "=r"(r[0]), "=r"(r[1]), "=r"(r[2]), "=r"(r[3])
      : "r"(addr));
}

__device__ __forceinline__ void cpa_commit() {
  asm volatile("cp.async.commit_group;\n" ::: "memory");
}
template <int N>
__device__ __forceinline__ void cpa_wait() {
  asm volatile("cp.async.wait_group %0;\n" ::"n"(N) : "memory");
}

// swizzled byte offset inside a 64-row x 128B tile (col in b16 elements)
__device__ __forceinline__ uint32_t swz(int row, int col) {
  return (uint32_t)((row << 7) + ((((col >> 3) ^ row) & 7) << 4) +
                    ((col & 7) << 1));
}

// cp.async one 64x128B plane (gmem row stride = strideB) into swizzled smem
__device__ __forceinline__ void cpa_tile(uint32_t sdst, const char* src,
                                         int strideB, int tid) {
#pragma unroll
  for (int i = 0; i < 4; ++i) {
    int c = tid + i * NTH;        // chunk 0..511
    int r = c >> 3, g = c & 7;
    uint32_t dst = sdst + (r << 7) + (((g ^ (r & 7)) & 7) << 4);
    const char* s = src + (long long)r * strideB + g * 16;
    asm volatile("cp.async.cg.shared.global [%0], [%1], 16;\n" ::"r"(dst),
                 "l"(s) : "memory");
  }
}

__device__ __forceinline__ void splitf(float x, __nv_bfloat16& h, __nv_bfloat16& l) {
  h = __float2bfloat16(x);
  l = __float2bfloat16(x - __bfloat162float(h));
}

// Q A-fragments via ldmatrix (hi + lo planes, swizzled tiles).
__device__ __forceinline__ void ld_qa(uint32_t bh, uint32_t bl, int lane, int w,
                                      uint32_t qa[2][4][4]) {
  int g = lane >> 3, rr = lane & 7;
  int row = w * 16 + (g & 1) * 8 + rr;
  int col0 = (g >> 1) * 8;
#pragma unroll
  for (int kk = 0; kk < 4; ++kk) {
    uint32_t off = swz(row, kk * 16 + col0);
    ldsm4(qa[0][kk], bh + off);
    ldsm4(qa[1][kk], bl + off);
  }
}

// One n8x2 block of S (m16 x n16 at n-block np) via 3-MMA bf16x2 emulation.
__device__ __forceinline__ void qk_np(float sA[4], float sB[4],
    const uint32_t qa[2][4][4], uint32_t kh, uint32_t kl,
    int np, int rowoff, int coloff) {
  sA[0] = sA[1] = sA[2] = sA[3] = 0.f;
  sB[0] = sB[1] = sB[2] = sB[3] = 0.f;
#pragma unroll
  for (int kk = 0; kk < 4; ++kk) {
    uint32_t off = swz(np * 16 + rowoff, kk * 16 + coloff);
    uint32_t bh[4], bl[4];
    ldsm4(bh, kh + off);
    ldsm4(bl, kl + off);
    mma16816(sA, qa[0][kk], bh[0], bh[1]);
    mma16816(sA, qa[0][kk], bl[0], bl[1]);
    mma16816(sA, qa[1][kk], bh[0], bh[1]);
    mma16816(sB, qa[0][kk], bh[2], bh[3]);
    mma16816(sB, qa[0][kk], bl[2], bl[3]);
    mma16816(sB, qa[1][kk], bh[2], bh[3]);
  }
}

// ====================== PREPROCESSING KERNELS =============================
// Q,K: fp32 [b,s,h,e] -> bf16 hi/lo [b,h,s,e]
__global__ void __launch_bounds__(256) conv_qk(const float* __restrict__ Q,
                                               const float* __restrict__ K) {
  long long lin = ((long long)blockIdx.x * 256 + threadIdx.x) * 4;
  int e = (int)(lin & 63);
  int h = (int)((lin >> 6) & 7);
  int s = (int)((lin >> 9) & 2047);
  int b = (int)(lin >> 20);
  long long doff = ((((long long)b * H_ + h) * 2048) + s) * 64 + e;
  float4 q = *reinterpret_cast<const float4*>(Q + lin);
  float4 k = *reinterpret_cast<const float4*>(K + lin);
  __nv_bfloat16 h0, l0, h1, l1, h2, l2, h3, l3;
  splitf(q.x, h0, l0); splitf(q.y, h1, l1); splitf(q.z, h2, l2); splitf(q.w, h3, l3);
  *reinterpret_cast<__nv_bfloat162*>(gQh + doff)     = __halves2bfloat162(h0, h1);
  *reinterpret_cast<__nv_bfloat162*>(gQh + doff + 2) = __halves2bfloat162(h2, h3);
  *reinterpret_cast<__nv_bfloat162*>(gQl + doff)     = __halves2bfloat162(l0, l1);
  *reinterpret_cast<__nv_bfloat162*>(gQl + doff + 2) = __halves2bfloat162(l2, l3);
  splitf(k.x, h0, l0); splitf(k.y, h1, l1); splitf(k.z, h2, l2); splitf(k.w, h3, l3);
  *reinterpret_cast<__nv_bfloat162*>(gKh + doff)     = __halves2bfloat162(h0, h1);
  *reinterpret_cast<__nv_bfloat162*>(gKh + doff + 2) = __halves2bfloat162(h2, h3);
  *reinterpret_cast<__nv_bfloat162*>(gKl + doff)     = __halves2bfloat162(l0, l1);
  *reinterpret_cast<__nv_bfloat162*>(gKl + doff + 2) = __halves2bfloat162(l2, l3);
}

// V: fp32 [b,s,h,e] -> fp16 transposed [b,h,e,s]
__global__ void __launch_bounds__(256) conv_v(const float* __restrict__ Vv) {
  __shared__ float t[64][65];
  int bh = blockIdx.x >> 5;        // b*8+h
  int s0 = (blockIdx.x & 31) * 64;
  int b = bh >> 3, h = bh & 7;
  int tid = threadIdx.x;
#pragma unroll
  for (int i = 0; i < 4; ++i) {
    int idx = tid + i * 256;
    int r = idx >> 4;
    int e4 = (idx & 15) << 2;
    float4 v = *reinterpret_cast<const float4*>(
        Vv + (((long long)b * 2048 + s0 + r) * H_ + h) * 64 + e4);
    t[e4][r] = v.x; t[e4 + 1][r] = v.y; t[e4 + 2][r] = v.z; t[e4 + 3][r] = v.w;
  }
  __syncthreads();
#pragma unroll
  for (int i = 0; i < 4; ++i) {
    int idx = tid + i * 256;
    int e = idx >> 4;
    int c4 = (idx & 15) << 2;
    __half2 a = __floats2half2_rn(t[e][c4], t[e][c4 + 1]);
    __half2 c = __floats2half2_rn(t[e][c4 + 2], t[e][c4 + 3]);
    uint2 w;
    memcpy(&w.x, &a, 4); memcpy(&w.y, &c, 4);
    *reinterpret_cast<uint2*>(gVt + ((long long)bh * 64 + e) * 2048 + s0 + c4) = w;
  }
}

// one block per 64-bit mask word; warp ballots
__global__ void __launch_bounds__(64) mask_bits(const int* __restrict__ mk) {
  __shared__ unsigned part[2];
  int t = threadIdx.x;
  int word = blockIdx.x;               // b*32 + jt
  int b = word >> 5, jt = word & 31;
  int v = mk[(long long)b * S_ + jt * 64 + t];
  unsigned bal = __ballot_sync(0xffffffffu, v != 0);
  if ((t & 31) == 0) part[t >> 5] = bal;
  __syncthreads();
  if (t == 0)
    g_mkbits[word] = (unsigned long long)part[0] |
                     ((unsigned long long)part[1] << 32);
}

// ============================ PASS 1 ======================================
// V output, entropy, invZ. Causal tiles only. cp.async 2-stage pipeline.
// smem: 2 stages x (Kh 8K | Kl 8K | Vf 8K) = 49152 B. 4 CTAs/SM.
__global__ void __launch_bounds__(NTH, 4) pass1_kernel(
    const int* __restrict__ mq, float* __restrict__ outV,
    float* __restrict__ outE) {
  __shared__ alignas(128) uint8_t smem[49152];

  const int blk = blockIdx.x;
  const int it = (NIT - 1) - (blk & (NIT - 1));  // big tiles first
  const int bh_ = blk >> 5;
  const int h = bh_ & 7;
  const long long b = bh_ >> 3;
  const int i0 = it * BQ;
  const int tid = threadIdx.x, w = tid >> 5, lane = tid & 31;
  const int qr = lane >> 2, qc = lane & 3;
  const int g = lane >> 3, rr = lane & 7;
  const int rowoff = (g >> 1) * 8 + rr, coloff = (g & 1) * 8;
  const int gi0 = i0 + w * 16 + qr, gi1 = gi0 + 8;

  const uint32_t shm = (uint32_t)__cvta_generic_to_shared(smem);
  const char* Kh_p = (const char*)(gKh + (long long)bh_ * 2048 * 64);
  const char* Kl_p = (const char*)(gKl + (long long)bh_ * 2048 * 64);
  const char* Vt_p = (const char*)(gVt + (long long)bh_ * 64 * 2048);
  const long long qoff = ((long long)bh_ * 2048 + i0) * 64;

  // Q -> stage0 Kh/Kl planes (group 0); K0/V0 -> stage1 (group 1)
  cpa_tile(shm,        (const char*)(gQh + qoff), 128, tid);
  cpa_tile(shm + 8192, (const char*)(gQl + qoff), 128, tid);
  cpa_commit();
  {
    uint32_t sb = shm + 24576;
    cpa_tile(sb,         Kh_p, 128, tid);
    cpa_tile(sb + 8192,  Kl_p, 128, tid);
    cpa_tile(sb + 16384, Vt_p, 4096, tid);
    cpa_commit();
  }
  cpa_wait<1>();
  __syncthreads();
  uint32_t qa[2][4][4];
  ld_qa(shm, shm + 8192, lane, w, qa);
  __syncthreads();
  if (it >= 1) {  // K1/V1 -> stage0
    cpa_tile(shm,         Kh_p + 8192, 128, tid);
    cpa_tile(shm + 8192,  Kl_p + 8192, 128, tid);
    cpa_tile(shm + 16384, Vt_p + 128,  4096, tid);
    cpa_commit();
  }

  float accO[8][4];
#pragma unroll
  for (int et = 0; et < 8; ++et)
    accO[et][0] = accO[et][1] = accO[et][2] = accO[et][3] = 0.f;
  float zac[2] = {0.f, 0.f}, eac[2] = {0.f, 0.f};

  for (int jt = 0; jt <= it; ++jt) {
    const int st = 1 - (jt & 1);
    const uint32_t sb = shm + st * 24576;
    const uint32_t vfb = sb + 16384;
    const unsigned long long mb = g_mkbits[b * NJT + jt];
    if (jt < it) cpa_wait<1>(); else cpa_wait<0>();
    __syncthreads();

    const int j0 = jt * BK;
    // fused: per n-block np -> QK, exp, PV (keeps score regs at 8)
#pragma unroll
    for (int np = 0; np < 4; ++np) {
      float sA[4], sB[4];
      qk_np(sA, sB, qa, sb, sb + 8192, np, rowoff, coloff);

      const int c0 = np * 16 + 2 * qc;    // sA cols; sB at +8
      const int gjA = j0 + c0;
      bool ka0 = ((mb >> c0) & 1ull) == 0;
      bool ka1 = ((mb >> (c0 + 1)) & 1ull) == 0;
      bool kb0 = ((mb >> (c0 + 8)) & 1ull) == 0;
      bool kb1 = ((mb >> (c0 + 9)) & 1ull) == 0;
      float a0 = sA[0] * SCALE, a1 = sA[1] * SCALE;
      float a2 = sA[2] * SCALE, a3 = sA[3] * SCALE;
      float b0 = sB[0] * SCALE, b1 = sB[1] * SCALE;
      float b2 = sB[2] * SCALE, b3 = sB[3] * SCALE;
      float eA0 = (ka0 && gjA     <= gi0) ? __expf(a0) : 0.f;
      float eA1 = (ka1 && gjA + 1 <= gi0) ? __expf(a1) : 0.f;
      float eA2 = (ka0 && gjA     <= gi1) ? __expf(a2) : 0.f;
      float eA3 = (ka1 && gjA + 1 <= gi1) ? __expf(a3) : 0.f;
      float eB0 = (kb0 && gjA + 8 <= gi0) ? __expf(b0) : 0.f;
      float eB1 = (kb1 && gjA + 9 <= gi0) ? __expf(b1) : 0.f;
      float eB2 = (kb0 && gjA + 8 <= gi1) ? __expf(b2) : 0.f;
      float eB3 = (kb1 && gjA + 9 <= gi1) ? __expf(b3) : 0.f;
      zac[0] += eA0 + eA1 + eB0 + eB1;
      zac[1] += eA2 + eA3 + eB2 + eB3;
      eac[0] += eA0 * a0 + eA1 * a1 + eB0 * b0 + eB1 * b1;
      eac[1] += eA2 * a2 + eA3 * a3 + eB2 * b2 + eB3 * b3;

      // P fragment (fp16) for PV; k-block of PV == np
      uint32_t ah[4];
      __half2 t0 = __floats2half2_rn(eA0, eA1);
      __half2 t1 = __floats2half2_rn(eA2, eA3);
      __half2 t2 = __floats2half2_rn(eB0, eB1);
      __half2 t3 = __floats2half2_rn(eB2, eB3);
      memcpy(&ah[0], &t0, 4); memcpy(&ah[1], &t1, 4);
      memcpy(&ah[2], &t2, 4); memcpy(&ah[3], &t3, 4);
#pragma unroll
      for (int ep = 0; ep < 4; ++ep) {
        uint32_t off = swz(ep * 16 + rowoff, np * 16 + coloff);
        uint32_t vf[4];
        ldsm4(vf, vfb + off);
        mma16816f(accO[2 * ep],     ah, vf[0], vf[1]);
        mma16816f(accO[2 * ep + 1], ah, vf[2], vf[3]);
      }
    }
    __syncthreads();
    if (jt + 2 <= it) {  // refill this stage with tile jt+2
      long long tb = (long long)(jt + 2) * 8192;
      cpa_tile(sb,         Kh_p + tb, 128, tid);
      cpa_tile(sb + 8192,  Kl_p + tb, 128, tid);
      cpa_tile(sb + 16384, Vt_p + (long long)(jt + 2) * 128, 4096, tid);
      cpa_commit();
    }
  }

  // ---- Row stats: quad reduction, entropy + invZ + V epilogue ------------
#pragma unroll
  for (int d = 1; d < 4; d <<= 1) {
    zac[0] += __shfl_xor_sync(0xffffffffu, zac[0], d);
    zac[1] += __shfl_xor_sync(0xffffffffu, zac[1], d);
    eac[0] += __shfl_xor_sync(0xffffffffu, eac[0], d);
    eac[1] += __shfl_xor_sync(0xffffffffu, eac[1], d);
  }
  const int mq0 = mq[b * L_ + gi0];
  const int mq1 = mq[b * L_ + gi1];
  const float inv0 = mq0 ? 0.f : 1.f / zac[0];
  const float inv1 = mq1 ? 0.f : 1.f / zac[1];

  if (qc == 0) {
    long long eb = (b * H_ + h) * L_;
    outE[eb + gi0] = mq0 ? 0.f : (__logf(zac[0]) - eac[0] * inv0);
    outE[eb + gi1] = mq1 ? 0.f : (__logf(zac[1]) - eac[1] * inv1);
    g_invZ[eb + gi0] = inv0;
    g_invZ[eb + gi1] = inv1;
  }
#pragma unroll
  for (int et = 0; et < 8; ++et) {
    int ge = et * 8 + 2 * qc;
    float2 v0 = {accO[et][0] * inv0, accO[et][1] * inv0};
    float2 v1 = {accO[et][2] * inv1, accO[et][3] * inv1};
    *reinterpret_cast<float2*>(&outV[((b * L_ + gi0) * H_ + h) * E_ + ge]) = v0;
    *reinterpret_cast<float2*>(&outV[((b * L_ + gi1) * H_ + h) * E_ + ge]) = v1;
  }
}

// ============================ PASS 2 ======================================
// Recompute scores, write A = e * invZ; zero-fill above the diagonal.
// smem: 2 stages x (Kh 8K | Kl 8K) = 32768 B. 5 CTAs/SM.
__global__ void __launch_bounds__(NTH, 5) pass2_kernel(float* __restrict__ outA) {
  __shared__ alignas(128) uint8_t smem[32768];

  const int blk = blockIdx.x;
  const int it = (NIT - 1) - (blk & (NIT - 1));
  const int bh_ = blk >> 5;
  const int h = bh_ & 7;
  const long long b = bh_ >> 3;
  const int i0 = it * BQ;
  const int tid = threadIdx.x, w = tid >> 5, lane = tid & 31;
  const int qr = lane >> 2, qc = lane & 3;
  const int g = lane >> 3, rr = lane & 7;
  const int rowoff = (g >> 1) * 8 + rr, coloff = (g & 1) * 8;
  const int gi0 = i0 + w * 16 + qr, gi1 = gi0 + 8;

  const uint32_t shm = (uint32_t)__cvta_generic_to_shared(smem);
  const char* Kh_p = (const char*)(gKh + (long long)bh_ * 2048 * 64);
  const char* Kl_p = (const char*)(gKl + (long long)bh_ * 2048 * 64);
  const long long qoff = ((long long)bh_ * 2048 + i0) * 64;

  cpa_tile(shm,        (const char*)(gQh + qoff), 128, tid);
  cpa_tile(shm + 8192, (const char*)(gQl + qoff), 128, tid);
  cpa_commit();
  {
    uint32_t sb = shm + 16384;
    cpa_tile(sb,        Kh_p, 128, tid);
    cpa_tile(sb + 8192, Kl_p, 128, tid);
    cpa_commit();
  }
  cpa_wait<1>();
  __syncthreads();
  uint32_t qa[2][4][4];
  ld_qa(shm, shm + 8192, lane, w, qa);
  __syncthreads();
  if (it >= 1) {
    cpa_tile(shm,        Kh_p + 8192, 128, tid);
    cpa_tile(shm + 8192, Kl_p + 8192, 128, tid);
    cpa_commit();
  }

  const float inv0 = g_invZ[(b * H_ + h) * L_ + gi0];
  const float inv1 = g_invZ[(b * H_ + h) * L_ + gi1];
  const long long aRow0 = ((b * H_ + h) * L_ + gi0) * S_;
  const long long aRow1 = aRow0 + 8LL * S_;

  for (int jt = 0; jt <= it; ++jt) {
    const int st = 1 - (jt & 1);
    const uint32_t sb = shm + st * 16384;
    const unsigned long long mb = g_mkbits[b * NJT + jt];
    if (jt < it) cpa_wait<1>(); else cpa_wait<0>();
    __syncthreads();

    const int j0 = jt * BK;
#pragma unroll
    for (int np = 0; np < 4; ++np) {
      float sA[4], sB[4];
      qk_np(sA, sB, qa, sb, sb + 8192, np, rowoff, coloff);

      const int c0 = np * 16 + 2 * qc;
      const int gjA = j0 + c0;
      bool ka0 = ((mb >> c0) & 1ull) == 0;
      bool ka1 = ((mb >> (c0 + 1)) & 1ull) == 0;
      bool kb0 = ((mb >> (c0 + 8)) & 1ull) == 0;
      bool kb1 = ((mb >> (c0 + 9)) & 1ull) == 0;
      float a0 = sA[0] * SCALE, a1 = sA[1] * SCALE;
      float a2 = sA[2] * SCALE, a3 = sA[3] * SCALE;
      float b0 = sB[0] * SCALE, b1 = sB[1] * SCALE;
      float b2 = sB[2] * SCALE, b3 = sB[3] * SCALE;
      float eA0 = (ka0 && gjA     <= gi0) ? __expf(a0) : 0.f;
      float eA1 = (ka1 && gjA + 1 <= gi0) ? __expf(a1) : 0.f;
      float eA2 = (ka0 && gjA     <= gi1) ? __expf(a2) : 0.f;
      float eA3 = (ka1 && gjA + 1 <= gi1) ? __expf(a3) : 0.f;
      float eB0 = (kb0 && gjA + 8 <= gi0) ? __expf(b0) : 0.f;
      float eB1 = (kb1 && gjA + 9 <= gi0) ? __expf(b1) : 0.f;
      float eB2 = (kb0 && gjA + 8 <= gi1) ? __expf(b2) : 0.f;
      float eB3 = (kb1 && gjA + 9 <= gi1) ? __expf(b3) : 0.f;
      float2 pA0 = {eA0 * inv0, eA1 * inv0};
      float2 pA1 = {eA2 * inv1, eA3 * inv1};
      float2 pB0 = {eB0 * inv0, eB1 * inv0};
      float2 pB1 = {eB2 * inv1, eB3 * inv1};
      *reinterpret_cast<float2*>(&outA[aRow0 + gjA])     = pA0;
      *reinterpret_cast<float2*>(&outA[aRow1 + gjA])     = pA1;
      *reinterpret_cast<float2*>(&outA[aRow0 + gjA + 8]) = pB0;
      *reinterpret_cast<float2*>(&outA[aRow1 + gjA + 8]) = pB1;
    }
    __syncthreads();
    if (jt + 2 <= it) {
      long long tb = (long long)(jt + 2) * 8192;
      cpa_tile(sb,        Kh_p + tb, 128, tid);
      cpa_tile(sb + 8192, Kl_p + tb, 128, tid);
      cpa_commit();
    }
  }

  // zero-fill fully causal-masked tiles
  const float4 z4 = {0.f, 0.f, 0.f, 0.f};
  for (int jt = it + 1; jt < NJT; ++jt) {
    const long long aBase = ((b * H_ + h) * L_ + i0) * S_ + jt * BK;
    for (int idx = tid; idx < BQ * (BK / 4); idx += NTH) {
      int row = idx >> 4;
      int c4 = (idx & 15) << 2;
      *reinterpret_cast<float4*>(&outA[aBase + (long long)row * S_ + c4]) = z4;
    }
  }
}

}  // namespace

extern "C" void kernel_launch(void* const* d_in, const int* in_sizes, int n_in,
                              void* d_out, int out_size) {
  const float* Q  = (const float*)d_in[0];
  const float* K  = (const float*)d_in[1];
  const float* Vv = (const float*)d_in[2];
  const int* mk   = (const int*)d_in[3];   // mask_miss_k (nonzero = missing)
  const int* mq   = (const int*)d_in[4];   // mask_miss_q
  float* out  = (float*)d_out;
  float* outV = out;
  float* outA = out + V_SZ;
  float* outE = out + V_SZ + A_SZ;

  conv_qk<<<2048, 256>>>(Q, K);
  conv_v<<<512, 256>>>(Vv);
  mask_bits<<<B_ * NJT, 64>>>(mk);
  dim3 grid(B_ * H_ * NIT);  // 512 blocks each
  pass1_kernel<<<grid, NTH>>>(mq, outV, outE);
  pass2_kernel<<<grid, NTH>>>(outA);
}

// round 11
// speedup vs baseline: 1.2046x; 1.2046x over previous
#include <cuda_runtime.h>
#include <cuda_bf16.h>
#include <cuda_fp16.h>
#include <cstdint>
#include <cstring>

namespace {

constexpr int B_ = 2, L_ = 2048, S_ = 2048, H_ = 8, E_ = 64;
constexpr int BQ = 64, BK = 64, NTH = 128;
constexpr int NIT = L_ / BQ;   // 32 query tiles
constexpr int NJT = S_ / BK;   // 32 key tiles
constexpr float SCALE = 0.125f;  // 1/sqrt(64)
constexpr long long V_SZ = (long long)B_ * L_ * H_ * E_;
constexpr long long A_SZ = (long long)B_ * H_ * L_ * S_;
constexpr long long NEL = (long long)B_ * H_ * 2048 * E_;  // 2,097,152

// ---- persistent scratch (device globals; no runtime allocation) ----------
__device__ __nv_bfloat16 gQh[NEL], gQl[NEL];   // [b,h,l,e]
__device__ __nv_bfloat16 gKh[NEL], gKl[NEL];   // [b,h,s,e]
__device__ __half gVt[NEL];                    // [b,h,e,s]
__device__ unsigned long long g_mkbits[B_ * NJT];
__device__ float g_invZ[B_ * H_ * L_];
// unnormalized exp values, fp16, blocked fragment layout:
// tile t = (bh*NIT + it)*NJT + jt; element (t*4 + qo)*128 + tid, uint4 each
__device__ uint4 gE[(long long)B_ * H_ * NIT * NJT * 4 * NTH];  // 134 MB

// ---- PTX helpers ---------------------------------------------------------
__device__ __forceinline__ void mma16816(float* c, const uint32_t* a,
                                         uint32_t b0, uint32_t b1) {
  asm volatile(
      "mma.sync.aligned.m16n8k16.row.col.f32.bf16.bf16.f32 "
      "{%0,%1,%2,%3}, {%4,%5,%6,%7}, {%8,%9}, {%0,%1,%2,%3};\n"
      : "+f"(c[0]), "+f"(c[1]), "+f"(c[2]), "+f"(c[3])
      : "r"(a[0]), "r"(a[1]), "r"(a[2]), "r"(a[3]), "r"(b0), "r"(b1));
}

__device__ __forceinline__ void mma16816f(float* c, const uint32_t* a,
                                          uint32_t b0, uint32_t b1) {
  asm volatile(
      "mma.sync.aligned.m16n8k16.row.col.f32.f16.f16.f32 "
      "{%0,%1,%2,%3}, {%4,%5,%6,%7}, {%8,%9}, {%0,%1,%2,%3};\n"
      : "+f"(c[0]), "+f"(c[1]), "+f"(c[2]), "+f"(c[3])
      : "r"(a[0]), "r"(a[1]), "r"(a[2]), "r"(a[3]), "r"(b0), "r"(b1));
}

__device__ __forceinline__ void ldsm4(uint32_t* r, uint32_t addr) {
  asm volatile(
      "ldmatrix.sync.aligned.m8n8.x4.shared.b16 {%0,%1,%2,%3}, [%4];\n"
      : "=r"(r[0]), "=r"(r[1]), "=r"(r[2]), "=r"(r[3])
      : "r"(addr));
}

__device__ __forceinline__ void cpa_commit() {
  asm volatile("cp.async.commit_group;\n" ::: "memory");
}
template <int N>
__device__ __forceinline__ void cpa_wait() {
  asm volatile("cp.async.wait_group %0;\n" ::"n"(N) : "memory");
}

// swizzled byte offset inside a 64-row x 128B tile (col in b16 elements)
__device__ __forceinline__ uint32_t swz(int row, int col) {
  return (uint32_t)((row << 7) + ((((col >> 3) ^ row) & 7) << 4) +
                    ((col & 7) << 1));
}

// cp.async one 64x128B plane (gmem row stride = strideB) into swizzled smem
__device__ __forceinline__ void cpa_tile(uint32_t sdst, const char* src,
                                         int strideB, int tid) {
#pragma unroll
  for (int i = 0; i < 4; ++i) {
    int c = tid + i * NTH;        // chunk 0..511
    int r = c >> 3, g = c & 7;
    uint32_t dst = sdst + (r << 7) + (((g ^ (r & 7)) & 7) << 4);
    const char* s = src + (long long)r * strideB + g * 16;
    asm volatile("cp.async.cg.shared.global [%0], [%1], 16;\n" ::"r"(dst),
                 "l"(s) : "memory");
  }
}

__device__ __forceinline__ void splitf(float x, __nv_bfloat16& h, __nv_bfloat16& l) {
  h = __float2bfloat16(x);
  l = __float2bfloat16(x - __bfloat162float(h));
}

__device__ __forceinline__ uint32_t packh2(float a, float b) {
  __half2 v = __floats2half2_rn(a, b);
  uint32_t r;
  memcpy(&r, &v, 4);
  return r;
}

// Q A-fragments via ldmatrix (hi + lo planes, swizzled tiles).
__device__ __forceinline__ void ld_qa(uint32_t bh, uint32_t bl, int lane, int w,
                                      uint32_t qa[2][4][4]) {
  int g = lane >> 3, rr = lane & 7;
  int row = w * 16 + (g & 1) * 8 + rr;
  int col0 = (g >> 1) * 8;
#pragma unroll
  for (int kk = 0; kk < 4; ++kk) {
    uint32_t off = swz(row, kk * 16 + col0);
    ldsm4(qa[0][kk], bh + off);
    ldsm4(qa[1][kk], bl + off);
  }
}

// S tile (per-warp m16 x n64) via 3-MMA bf16x2 emulation.
__device__ __forceinline__ void qk_tile(float sc[8][4], const uint32_t qa[2][4][4],
    uint32_t kh, uint32_t kl, int rowoff, int coloff) {
#pragma unroll
  for (int nt = 0; nt < 8; ++nt)
    sc[nt][0] = sc[nt][1] = sc[nt][2] = sc[nt][3] = 0.f;
#pragma unroll
  for (int np = 0; np < 4; ++np) {
#pragma unroll
    for (int kk = 0; kk < 4; ++kk) {
      uint32_t off = swz(np * 16 + rowoff, kk * 16 + coloff);
      uint32_t bh[4], bl[4];
      ldsm4(bh, kh + off);
      ldsm4(bl, kl + off);
      mma16816(sc[2 * np],     qa[0][kk], bh[0], bh[1]);
      mma16816(sc[2 * np],     qa[0][kk], bl[0], bl[1]);
      mma16816(sc[2 * np],     qa[1][kk], bh[0], bh[1]);
      mma16816(sc[2 * np + 1], qa[0][kk], bh[2], bh[3]);
      mma16816(sc[2 * np + 1], qa[0][kk], bl[2], bl[3]);
      mma16816(sc[2 * np + 1], qa[1][kk], bh[2], bh[3]);
    }
  }
}

// ====================== PREPROCESSING KERNELS =============================
// Q,K: fp32 [b,s,h,e] -> bf16 hi/lo [b,h,s,e]
__global__ void __launch_bounds__(256) conv_qk(const float* __restrict__ Q,
                                               const float* __restrict__ K) {
  long long lin = ((long long)blockIdx.x * 256 + threadIdx.x) * 4;
  int e = (int)(lin & 63);
  int h = (int)((lin >> 6) & 7);
  int s = (int)((lin >> 9) & 2047);
  int b = (int)(lin >> 20);
  long long doff = ((((long long)b * H_ + h) * 2048) + s) * 64 + e;
  float4 q = *reinterpret_cast<const float4*>(Q + lin);
  float4 k = *reinterpret_cast<const float4*>(K + lin);
  __nv_bfloat16 h0, l0, h1, l1, h2, l2, h3, l3;
  splitf(q.x, h0, l0); splitf(q.y, h1, l1); splitf(q.z, h2, l2); splitf(q.w, h3, l3);
  *reinterpret_cast<__nv_bfloat162*>(gQh + doff)     = __halves2bfloat162(h0, h1);
  *reinterpret_cast<__nv_bfloat162*>(gQh + doff + 2) = __halves2bfloat162(h2, h3);
  *reinterpret_cast<__nv_bfloat162*>(gQl + doff)     = __halves2bfloat162(l0, l1);
  *reinterpret_cast<__nv_bfloat162*>(gQl + doff + 2) = __halves2bfloat162(l2, l3);
  splitf(k.x, h0, l0); splitf(k.y, h1, l1); splitf(k.z, h2, l2); splitf(k.w, h3, l3);
  *reinterpret_cast<__nv_bfloat162*>(gKh + doff)     = __halves2bfloat162(h0, h1);
  *reinterpret_cast<__nv_bfloat162*>(gKh + doff + 2) = __halves2bfloat162(h2, h3);
  *reinterpret_cast<__nv_bfloat162*>(gKl + doff)     = __halves2bfloat162(l0, l1);
  *reinterpret_cast<__nv_bfloat162*>(gKl + doff + 2) = __halves2bfloat162(l2, l3);
}

// V: fp32 [b,s,h,e] -> fp16 transposed [b,h,e,s]
__global__ void __launch_bounds__(256) conv_v(const float* __restrict__ Vv) {
  __shared__ float t[64][65];
  int bh = blockIdx.x >> 5;        // b*8+h
  int s0 = (blockIdx.x & 31) * 64;
  int b = bh >> 3, h = bh & 7;
  int tid = threadIdx.x;
#pragma unroll
  for (int i = 0; i < 4; ++i) {
    int idx = tid + i * 256;
    int r = idx >> 4;
    int e4 = (idx & 15) << 2;
    float4 v = *reinterpret_cast<const float4*>(
        Vv + (((long long)b * 2048 + s0 + r) * H_ + h) * 64 + e4);
    t[e4][r] = v.x; t[e4 + 1][r] = v.y; t[e4 + 2][r] = v.z; t[e4 + 3][r] = v.w;
  }
  __syncthreads();
#pragma unroll
  for (int i = 0; i < 4; ++i) {
    int idx = tid + i * 256;
    int e = idx >> 4;
    int c4 = (idx & 15) << 2;
    __half2 a = __floats2half2_rn(t[e][c4], t[e][c4 + 1]);
    __half2 c = __floats2half2_rn(t[e][c4 + 2], t[e][c4 + 3]);
    uint2 w;
    memcpy(&w.x, &a, 4); memcpy(&w.y, &c, 4);
    *reinterpret_cast<uint2*>(gVt + ((long long)bh * 64 + e) * 2048 + s0 + c4) = w;
  }
}

// one block per 64-bit mask word; warp ballots
__global__ void __launch_bounds__(64) mask_bits(const int* __restrict__ mk) {
  __shared__ unsigned part[2];
  int t = threadIdx.x;
  int word = blockIdx.x;               // b*32 + jt
  int b = word >> 5, jt = word & 31;
  int v = mk[(long long)b * S_ + jt * 64 + t];
  unsigned bal = __ballot_sync(0xffffffffu, v != 0);
  if ((t & 31) == 0) part[t >> 5] = bal;
  __syncthreads();
  if (t == 0)
    g_mkbits[word] = (unsigned long long)part[0] |
                     ((unsigned long long)part[1] << 32);
}

// ============================ PASS 1 ======================================
// V output, entropy, invZ + unnormalized e -> gE (fp16, blocked layout).
// Causal tiles only. cp.async 2-stage pipeline. Round-7 proven structure.
__global__ void __launch_bounds__(NTH, 3) pass1_kernel(
    const int* __restrict__ mq, float* __restrict__ outV,
    float* __restrict__ outE) {
  __shared__ alignas(128) uint8_t smem[49152];

  const int blk = blockIdx.x;
  const int it = (NIT - 1) - (blk & (NIT - 1));  // big tiles first
  const int bh_ = blk >> 5;
  const int h = bh_ & 7;
  const long long b = bh_ >> 3;
  const int i0 = it * BQ;
  const int tid = threadIdx.x, w = tid >> 5, lane = tid & 31;
  const int qr = lane >> 2, qc = lane & 3;
  const int g = lane >> 3, rr = lane & 7;
  const int rowoff = (g >> 1) * 8 + rr, coloff = (g & 1) * 8;
  const int gi0 = i0 + w * 16 + qr, gi1 = gi0 + 8;

  const uint32_t shm = (uint32_t)__cvta_generic_to_shared(smem);
  const char* Kh_p = (const char*)(gKh + (long long)bh_ * 2048 * 64);
  const char* Kl_p = (const char*)(gKl + (long long)bh_ * 2048 * 64);
  const char* Vt_p = (const char*)(gVt + (long long)bh_ * 64 * 2048);
  const long long qoff = ((long long)bh_ * 2048 + i0) * 64;

  // Q -> stage0 Kh/Kl planes (group 0); K0/V0 -> stage1 (group 1)
  cpa_tile(shm,        (const char*)(gQh + qoff), 128, tid);
  cpa_tile(shm + 8192, (const char*)(gQl + qoff), 128, tid);
  cpa_commit();
  {
    uint32_t sb = shm + 24576;
    cpa_tile(sb,         Kh_p, 128, tid);
    cpa_tile(sb + 8192,  Kl_p, 128, tid);
    cpa_tile(sb + 16384, Vt_p, 4096, tid);
    cpa_commit();
  }
  cpa_wait<1>();
  __syncthreads();
  uint32_t qa[2][4][4];
  ld_qa(shm, shm + 8192, lane, w, qa);
  __syncthreads();
  if (it >= 1) {  // K1/V1 -> stage0
    cpa_tile(shm,         Kh_p + 8192, 128, tid);
    cpa_tile(shm + 8192,  Kl_p + 8192, 128, tid);
    cpa_tile(shm + 16384, Vt_p + 128,  4096, tid);
    cpa_commit();
  }

  float accO[8][4];
#pragma unroll
  for (int et = 0; et < 8; ++et)
    accO[et][0] = accO[et][1] = accO[et][2] = accO[et][3] = 0.f;
  float zac[2] = {0.f, 0.f}, eac[2] = {0.f, 0.f};

  const long long tile0 = (long long)(bh_ * NIT + it) * NJT;

  for (int jt = 0; jt <= it; ++jt) {
    const int st = 1 - (jt & 1);
    const uint32_t sb = shm + st * 24576;
    const uint32_t vfb = sb + 16384;
    const unsigned long long mb = g_mkbits[b * NJT + jt];
    if (jt < it) cpa_wait<1>(); else cpa_wait<0>();
    __syncthreads();

    const int j0 = jt * BK;
    float sc[8][4];
    qk_tile(sc, qa, sb, sb + 8192, rowoff, coloff);

#pragma unroll
    for (int nt = 0; nt < 8; ++nt) {
      int c0 = nt * 8 + 2 * qc;
      int gj = j0 + c0;
      bool kv0 = ((mb >> c0) & 1ull) == 0;
      bool kv1 = ((mb >> (c0 + 1)) & 1ull) == 0;
      float s0 = sc[nt][0] * SCALE, s1 = sc[nt][1] * SCALE;
      float s2 = sc[nt][2] * SCALE, s3 = sc[nt][3] * SCALE;
      float e0 = (kv0 && gj     <= gi0) ? __expf(s0) : 0.f;
      float e1 = (kv1 && gj + 1 <= gi0) ? __expf(s1) : 0.f;
      float e2 = (kv0 && gj     <= gi1) ? __expf(s2) : 0.f;
      float e3 = (kv1 && gj + 1 <= gi1) ? __expf(s3) : 0.f;
      zac[0] += e0 + e1;           zac[1] += e2 + e3;
      eac[0] += e0 * s0 + e1 * s1; eac[1] += e2 * s2 + e3 * s3;
      sc[nt][0] = e0; sc[nt][1] = e1; sc[nt][2] = e2; sc[nt][3] = e3;
    }

    // store unnormalized e to gE (fp16, fragment-ordered, coalesced 128B/warp)
    {
      uint4* dst = gE + (tile0 + jt) * 4 * NTH + tid;
#pragma unroll
      for (int qo = 0; qo < 4; ++qo) {
        uint4 v;
        v.x = packh2(sc[2 * qo][0],     sc[2 * qo][1]);
        v.y = packh2(sc[2 * qo][2],     sc[2 * qo][3]);
        v.z = packh2(sc[2 * qo + 1][0], sc[2 * qo + 1][1]);
        v.w = packh2(sc[2 * qo + 1][2], sc[2 * qo + 1][3]);
        dst[qo * NTH] = v;
      }
    }

    // PV in fp16: P (C-layout) -> A operand; V fragments via ldmatrix.
#pragma unroll
    for (int kk = 0; kk < 4; ++kk) {
      const float* cA = sc[2 * kk];
      const float* cB = sc[2 * kk + 1];
      uint32_t ah[4];
      ah[0] = packh2(cA[0], cA[1]);
      ah[1] = packh2(cA[2], cA[3]);
      ah[2] = packh2(cB[0], cB[1]);
      ah[3] = packh2(cB[2], cB[3]);
#pragma unroll
      for (int ep = 0; ep < 4; ++ep) {
        uint32_t off = swz(ep * 16 + rowoff, kk * 16 + coloff);
        uint32_t vf[4];
        ldsm4(vf, vfb + off);
        mma16816f(accO[2 * ep],     ah, vf[0], vf[1]);
        mma16816f(accO[2 * ep + 1], ah, vf[2], vf[3]);
      }
    }
    __syncthreads();
    if (jt + 2 <= it) {  // refill this stage with tile jt+2
      long long tb = (long long)(jt + 2) * 8192;
      cpa_tile(sb,         Kh_p + tb, 128, tid);
      cpa_tile(sb + 8192,  Kl_p + tb, 128, tid);
      cpa_tile(sb + 16384, Vt_p + (long long)(jt + 2) * 128, 4096, tid);
      cpa_commit();
    }
  }

  // ---- Row stats: quad reduction, entropy + invZ + V epilogue ------------
#pragma unroll
  for (int d = 1; d < 4; d <<= 1) {
    zac[0] += __shfl_xor_sync(0xffffffffu, zac[0], d);
    zac[1] += __shfl_xor_sync(0xffffffffu, zac[1], d);
    eac[0] += __shfl_xor_sync(0xffffffffu, eac[0], d);
    eac[1] += __shfl_xor_sync(0xffffffffu, eac[1], d);
  }
  const int mq0 = mq[b * L_ + gi0];
  const int mq1 = mq[b * L_ + gi1];
  const float inv0 = mq0 ? 0.f : 1.f / zac[0];
  const float inv1 = mq1 ? 0.f : 1.f / zac[1];

  if (qc == 0) {
    long long eb = (b * H_ + h) * L_;
    outE[eb + gi0] = mq0 ? 0.f : (__logf(zac[0]) - eac[0] * inv0);
    outE[eb + gi1] = mq1 ? 0.f : (__logf(zac[1]) - eac[1] * inv1);
    g_invZ[eb + gi0] = inv0;
    g_invZ[eb + gi1] = inv1;
  }
#pragma unroll
  for (int et = 0; et < 8; ++et) {
    int ge = et * 8 + 2 * qc;
    float2 v0 = {accO[et][0] * inv0, accO[et][1] * inv0};
    float2 v1 = {accO[et][2] * inv1, accO[et][3] * inv1};
    *reinterpret_cast<float2*>(&outV[((b * L_ + gi0) * H_ + h) * E_ + ge]) = v0;
    *reinterpret_cast<float2*>(&outV[((b * L_ + gi1) * H_ + h) * E_ + ge]) = v1;
  }
}

// ============================ PASS 2 ======================================
// Pure memory: A = gE * invZ (lower triangle) + zero fill (upper). No MMA.
__global__ void __launch_bounds__(NTH) pass2_kernel(float* __restrict__ outA) {
  const int blk = blockIdx.x;
  const int it = blk & (NIT - 1);      // naturally balanced: 32 tile-ops each
  const int bh_ = blk >> 5;
  const int i0 = it * BQ;
  const int tid = threadIdx.x, w = tid >> 5, lane = tid & 31;
  const int qr = lane >> 2, qc = lane & 3;
  const int gi0 = i0 + w * 16 + qr, gi1 = gi0 + 8;

  const float inv0 = g_invZ[(long long)bh_ * L_ + gi0];
  const float inv1 = g_invZ[(long long)bh_ * L_ + gi1];
  const long long aRow0 = ((long long)bh_ * L_ + gi0) * S_;
  const long long aRow1 = aRow0 + 8LL * S_;
  const long long tile0 = (long long)(bh_ * NIT + it) * NJT;

  for (int jt = 0; jt <= it; ++jt) {
    const int j0 = jt * BK;
    const uint4* src = gE + (tile0 + jt) * 4 * NTH + tid;
#pragma unroll
    for (int qo = 0; qo < 4; ++qo) {
      uint4 v = src[qo * NTH];
      int cA = j0 + (2 * qo) * 8 + 2 * qc;
      int cB = cA + 8;
      float2 fA0 = __half22float2(*reinterpret_cast<__half2*>(&v.x));
      float2 fA1 = __half22float2(*reinterpret_cast<__half2*>(&v.y));
      float2 fB0 = __half22float2(*reinterpret_cast<__half2*>(&v.z));
      float2 fB1 = __half22float2(*reinterpret_cast<__half2*>(&v.w));
      float2 pA0 = {fA0.x * inv0, fA0.y * inv0};
      float2 pA1 = {fA1.x * inv1, fA1.y * inv1};
      float2 pB0 = {fB0.x * inv0, fB0.y * inv0};
      float2 pB1 = {fB1.x * inv1, fB1.y * inv1};
      *reinterpret_cast<float2*>(&outA[aRow0 + cA]) = pA0;
      *reinterpret_cast<float2*>(&outA[aRow1 + cA]) = pA1;
      *reinterpret_cast<float2*>(&outA[aRow0 + cB]) = pB0;
      *reinterpret_cast<float2*>(&outA[aRow1 + cB]) = pB1;
    }
  }

  // zero-fill fully causal-masked tiles
  const float4 z4 = {0.f, 0.f, 0.f, 0.f};
  for (int jt = it + 1; jt < NJT; ++jt) {
    const long long aBase = ((long long)bh_ * L_ + i0) * S_ + jt * BK;
    for (int idx = tid; idx < BQ * (BK / 4); idx += NTH) {
      int row = idx >> 4;
      int c4 = (idx & 15) << 2;
      *reinterpret_cast<float4*>(&outA[aBase + (long long)row * S_ + c4]) = z4;
    }
  }
}

}  // namespace

extern "C" void kernel_launch(void* const* d_in, const int* in_sizes, int n_in,
                              void* d_out, int out_size) {
  const float* Q  = (const float*)d_in[0];
  const float* K  = (const float*)d_in[1];
  const float* Vv = (const float*)d_in[2];
  const int* mk   = (const int*)d_in[3];   // mask_miss_k (nonzero = missing)
  const int* mq   = (const int*)d_in[4];   // mask_miss_q
  float* out  = (float*)d_out;
  float* outV = out;
  float* outA = out + V_SZ;
  float* outE = out + V_SZ + A_SZ;

  conv_qk<<<2048, 256>>>(Q, K);
  conv_v<<<512, 256>>>(Vv);
  mask_bits<<<B_ * NJT, 64>>>(mk);
  dim3 grid(B_ * H_ * NIT);  // 512 blocks each
  pass1_kernel<<<grid, NTH>>>(mq, outV, outE);
  pass2_kernel<<<grid, NTH>>>(outA);
}

// round 17
// speedup vs baseline: 1.2438x; 1.0325x over previous
#include <cuda_runtime.h>
#include <cuda_bf16.h>
#include <cuda_fp16.h>
#include <cstdint>
#include <cstring>

namespace {

constexpr int B_ = 2, L_ = 2048, S_ = 2048, H_ = 8, E_ = 64;
constexpr int BQ = 64, BK = 64, NTH = 128;
constexpr int NIT = L_ / BQ;   // 32 query tiles
constexpr int NJT = S_ / BK;   // 32 key tiles
constexpr float SCALE = 0.125f;  // 1/sqrt(64)
constexpr long long V_SZ = (long long)B_ * L_ * H_ * E_;
constexpr long long A_SZ = (long long)B_ * H_ * L_ * S_;
constexpr long long NEL = (long long)B_ * H_ * 2048 * E_;  // 2,097,152
constexpr int NCTA1 = 48;      // pass1 dispatch table entries per bh

// ---- persistent scratch (device globals; no runtime allocation) ----------
__device__ __nv_bfloat16 gQh[NEL], gQl[NEL];   // [b,h,l,e]
__device__ __nv_bfloat16 gKh[NEL], gKl[NEL];   // [b,h,s,e]
__device__ __half gVt[NEL];                    // [b,h,e,s]
__device__ unsigned long long g_mkbits[B_ * NJT];
__device__ float g_invZ[B_ * H_ * L_];
// unnormalized exp values, fp16, blocked fragment layout:
// tile t = (bh*NIT + it)*NJT + jt; element (t*4 + qo)*128 + tid, uint4 each
__device__ uint4 gE[(long long)B_ * H_ * NIT * NJT * 4 * NTH];  // 134 MB
// split-K partials for it>=16: slot = (bh*16 + (it-16))*2 + half
__device__ float gPZ[16 * 16 * 2 * 64];
__device__ float gPE[16 * 16 * 2 * 64];
__device__ float4 gPO[16 * 16 * 2 * 1024];     // 8.4 MB

// LPT-ordered dispatch: it>=16 split into [0,(it+1)/2) and [(it+1)/2,it+1)
__constant__ unsigned char tab_it[NCTA1] = {
    31, 31, 30, 15, 30, 29, 29, 28, 14, 28, 27, 27, 26, 13, 26, 25,
    25, 24, 12, 24, 23, 23, 22, 11, 22, 21, 21, 20, 10, 20, 19, 19,
    18,  9, 18, 17, 17, 16,  8, 16,  7,  6,  5,  4,  3,  2,  1,  0};
__constant__ unsigned char tab_j0[NCTA1] = {
     0, 16, 15,  0,  0,  0, 15, 14,  0,  0,  0, 14, 13,  0,  0,  0,
    13, 12,  0,  0,  0, 12, 11,  0,  0,  0, 11, 10,  0,  0,  0, 10,
     9,  0,  0,  0,  9,  8,  0,  0,  0,  0,  0,  0,  0,  0,  0,  0};
__constant__ unsigned char tab_j1[NCTA1] = {
    16, 32, 31, 16, 15, 15, 30, 29, 15, 14, 14, 28, 27, 14, 13, 13,
    26, 25, 13, 12, 12, 24, 23, 12, 11, 11, 22, 21, 11, 10, 10, 20,
    19, 10,  9,  9, 18, 17,  9,  8,  8,  7,  6,  5,  4,  3,  2,  1};

// ---- PTX helpers ---------------------------------------------------------
__device__ __forceinline__ void mma16816(float* c, const uint32_t* a,
                                         uint32_t b0, uint32_t b1) {
  asm volatile(
      "mma.sync.aligned.m16n8k16.row.col.f32.bf16.bf16.f32 "
      "{%0,%1,%2,%3}, {%4,%5,%6,%7}, {%8,%9}, {%0,%1,%2,%3};\n"
      : "+f"(c[0]), "+f"(c[1]), "+f"(c[2]), "+f"(c[3])
      : "r"(a[0]), "r"(a[1]), "r"(a[2]), "r"(a[3]), "r"(b0), "r"(b1));
}

__device__ __forceinline__ void mma16816f(float* c, const uint32_t* a,
                                          uint32_t b0, uint32_t b1) {
  asm volatile(
      "mma.sync.aligned.m16n8k16.row.col.f32.f16.f16.f32 "
      "{%0,%1,%2,%3}, {%4,%5,%6,%7}, {%8,%9}, {%0,%1,%2,%3};\n"
      : "+f"(c[0]), "+f"(c[1]), "+f"(c[2]), "+f"(c[3])
      : "r"(a[0]), "r"(a[1]), "r"(a[2]), "r"(a[3]), "r"(b0), "r"(b1));
}

__device__ __forceinline__ void ldsm4(uint32_t* r, uint32_t addr) {
  asm volatile(
      "ldmatrix.sync.aligned.m8n8.x4.shared.b16 {%0,%1,%2,%3}, [%4];\n"
      : "=r"(r[0]), "=r"(r[1]), "=r"(r[2]), "=r"(r[3])
      : "r"(addr));
}

__device__ __forceinline__ void cpa_commit() {
  asm volatile("cp.async.commit_group;\n" ::: "memory");
}
template <int N>
__device__ __forceinline__ void cpa_wait() {
  asm volatile("cp.async.wait_group %0;\n" ::"n"(N) : "memory");
}

// swizzled byte offset inside a 64-row x 128B tile (col in b16 elements)
__device__ __forceinline__ uint32_t swz(int row, int col) {
  return (uint32_t)((row << 7) + ((((col >> 3) ^ row) & 7) << 4) +
                    ((col & 7) << 1));
}

// cp.async one 64x128B plane (gmem row stride = strideB) into swizzled smem
__device__ __forceinline__ void cpa_tile(uint32_t sdst, const char* src,
                                         int strideB, int tid) {
#pragma unroll
  for (int i = 0; i < 4; ++i) {
    int c = tid + i * NTH;        // chunk 0..511
    int r = c >> 3, g = c & 7;
    uint32_t dst = sdst + (r << 7) + (((g ^ (r & 7)) & 7) << 4);
    const char* s = src + (long long)r * strideB + g * 16;
    asm volatile("cp.async.cg.shared.global [%0], [%1], 16;\n" ::"r"(dst),
                 "l"(s) : "memory");
  }
}

__device__ __forceinline__ void splitf(float x, __nv_bfloat16& h, __nv_bfloat16& l) {
  h = __float2bfloat16(x);
  l = __float2bfloat16(x - __bfloat162float(h));
}

__device__ __forceinline__ uint32_t packh2(float a, float b) {
  __half2 v = __floats2half2_rn(a, b);
  uint32_t r;
  memcpy(&r, &v, 4);
  return r;
}

// Q A-fragments via ldmatrix (hi + lo planes, swizzled tiles).
__device__ __forceinline__ void ld_qa(uint32_t bh, uint32_t bl, int lane, int w,
                                      uint32_t qa[2][4][4]) {
  int g = lane >> 3, rr = lane & 7;
  int row = w * 16 + (g & 1) * 8 + rr;
  int col0 = (g >> 1) * 8;
#pragma unroll
  for (int kk = 0; kk < 4; ++kk) {
    uint32_t off = swz(row, kk * 16 + col0);
    ldsm4(qa[0][kk], bh + off);
    ldsm4(qa[1][kk], bl + off);
  }
}

// S tile (per-warp m16 x n64) via 3-MMA bf16x2 emulation.
__device__ __forceinline__ void qk_tile(float sc[8][4], const uint32_t qa[2][4][4],
    uint32_t kh, uint32_t kl, int rowoff, int coloff) {
#pragma unroll
  for (int nt = 0; nt < 8; ++nt)
    sc[nt][0] = sc[nt][1] = sc[nt][2] = sc[nt][3] = 0.f;
#pragma unroll
  for (int np = 0; np < 4; ++np) {
#pragma unroll
    for (int kk = 0; kk < 4; ++kk) {
      uint32_t off = swz(np * 16 + rowoff, kk * 16 + coloff);
      uint32_t bh[4], bl[4];
      ldsm4(bh, kh + off);
      ldsm4(bl, kl + off);
      mma16816(sc[2 * np],     qa[0][kk], bh[0], bh[1]);
      mma16816(sc[2 * np],     qa[0][kk], bl[0], bl[1]);
      mma16816(sc[2 * np],     qa[1][kk], bh[0], bh[1]);
      mma16816(sc[2 * np + 1], qa[0][kk], bh[2], bh[3]);
      mma16816(sc[2 * np + 1], qa[0][kk], bl[2], bl[3]);
      mma16816(sc[2 * np + 1], qa[1][kk], bh[2], bh[3]);
    }
  }
}

// ====================== PREPROCESSING KERNELS =============================
// Q,K: fp32 [b,s,h,e] -> bf16 hi/lo [b,h,s,e]
__global__ void __launch_bounds__(256) conv_qk(const float* __restrict__ Q,
                                               const float* __restrict__ K) {
  long long lin = ((long long)blockIdx.x * 256 + threadIdx.x) * 4;
  int e = (int)(lin & 63);
  int h = (int)((lin >> 6) & 7);
  int s = (int)((lin >> 9) & 2047);
  int b = (int)(lin >> 20);
  long long doff = ((((long long)b * H_ + h) * 2048) + s) * 64 + e;
  float4 q = *reinterpret_cast<const float4*>(Q + lin);
  float4 k = *reinterpret_cast<const float4*>(K + lin);
  __nv_bfloat16 h0, l0, h1, l1, h2, l2, h3, l3;
  splitf(q.x, h0, l0); splitf(q.y, h1, l1); splitf(q.z, h2, l2); splitf(q.w, h3, l3);
  *reinterpret_cast<__nv_bfloat162*>(gQh + doff)     = __halves2bfloat162(h0, h1);
  *reinterpret_cast<__nv_bfloat162*>(gQh + doff + 2) = __halves2bfloat162(h2, h3);
  *reinterpret_cast<__nv_bfloat162*>(gQl + doff)     = __halves2bfloat162(l0, l1);
  *reinterpret_cast<__nv_bfloat162*>(gQl + doff + 2) = __halves2bfloat162(l2, l3);
  splitf(k.x, h0, l0); splitf(k.y, h1, l1); splitf(k.z, h2, l2); splitf(k.w, h3, l3);
  *reinterpret_cast<__nv_bfloat162*>(gKh + doff)     = __halves2bfloat162(h0, h1);
  *reinterpret_cast<__nv_bfloat162*>(gKh + doff + 2) = __halves2bfloat162(h2, h3);
  *reinterpret_cast<__nv_bfloat162*>(gKl + doff)     = __halves2bfloat162(l0, l1);
  *reinterpret_cast<__nv_bfloat162*>(gKl + doff + 2) = __halves2bfloat162(l2, l3);
}

// V: fp32 [b,s,h,e] -> fp16 transposed [b,h,e,s]
__global__ void __launch_bounds__(256) conv_v(const float* __restrict__ Vv) {
  __shared__ float t[64][65];
  int bh = blockIdx.x >> 5;        // b*8+h
  int s0 = (blockIdx.x & 31) * 64;
  int b = bh >> 3, h = bh & 7;
  int tid = threadIdx.x;
#pragma unroll
  for (int i = 0; i < 4; ++i) {
    int idx = tid + i * 256;
    int r = idx >> 4;
    int e4 = (idx & 15) << 2;
    float4 v = *reinterpret_cast<const float4*>(
        Vv + (((long long)b * 2048 + s0 + r) * H_ + h) * 64 + e4);
    t[e4][r] = v.x; t[e4 + 1][r] = v.y; t[e4 + 2][r] = v.z; t[e4 + 3][r] = v.w;
  }
  __syncthreads();
#pragma unroll
  for (int i = 0; i < 4; ++i) {
    int idx = tid + i * 256;
    int e = idx >> 4;
    int c4 = (idx & 15) << 2;
    __half2 a = __floats2half2_rn(t[e][c4], t[e][c4 + 1]);
    __half2 c = __floats2half2_rn(t[e][c4 + 2], t[e][c4 + 3]);
    uint2 w;
    memcpy(&w.x, &a, 4); memcpy(&w.y, &c, 4);
    *reinterpret_cast<uint2*>(gVt + ((long long)bh * 64 + e) * 2048 + s0 + c4) = w;
  }
}

// one block per 64-bit mask word; warp ballots
__global__ void __launch_bounds__(64) mask_bits(const int* __restrict__ mk) {
  __shared__ unsigned part[2];
  int t = threadIdx.x;
  int word = blockIdx.x;               // b*32 + jt
  int b = word >> 5, jt = word & 31;
  int v = mk[(long long)b * S_ + jt * 64 + t];
  unsigned bal = __ballot_sync(0xffffffffu, v != 0);
  if ((t & 31) == 0) part[t >> 5] = bal;
  __syncthreads();
  if (t == 0)
    g_mkbits[word] = (unsigned long long)part[0] |
                     ((unsigned long long)part[1] << 32);
}

// ============================ PASS 1 ======================================
// it<16: full causal range, finalize V/E/invZ inline.
// it>=16: half the jt range per CTA; partials to gPZ/gPE/gPO.
// Also stores unnormalized e -> gE for every processed tile.
__global__ void __launch_bounds__(NTH, 3) pass1_kernel(
    const int* __restrict__ mq, float* __restrict__ outV,
    float* __restrict__ outE) {
  __shared__ alignas(128) uint8_t smem[49152];

  const int blk = blockIdx.x;
  const int c = blk >> 4;              // 0..47 dispatch entry (LPT order)
  const int bh_ = blk & 15;
  const int it = tab_it[c];
  const int j0t = tab_j0[c];
  const int j1t = tab_j1[c];
  const int ntile = j1t - j0t;
  const bool is_split = (ntile != it + 1);
  const int h = bh_ & 7;
  const long long b = bh_ >> 3;
  const int i0 = it * BQ;
  const int tid = threadIdx.x, w = tid >> 5, lane = tid & 31;
  const int qr = lane >> 2, qc = lane & 3;
  const int g = lane >> 3, rr = lane & 7;
  const int rowoff = (g >> 1) * 8 + rr, coloff = (g & 1) * 8;
  const int gi0 = i0 + w * 16 + qr, gi1 = gi0 + 8;

  const uint32_t shm = (uint32_t)__cvta_generic_to_shared(smem);
  const char* Kh_p = (const char*)(gKh + (long long)bh_ * 2048 * 64);
  const char* Kl_p = (const char*)(gKl + (long long)bh_ * 2048 * 64);
  const char* Vt_p = (const char*)(gVt + (long long)bh_ * 64 * 2048);
  const long long qoff = ((long long)bh_ * 2048 + i0) * 64;

  // Q -> stage0 planes (group 0); K(j0t)/V(j0t) -> stage1 (group 1)
  cpa_tile(shm,        (const char*)(gQh + qoff), 128, tid);
  cpa_tile(shm + 8192, (const char*)(gQl + qoff), 128, tid);
  cpa_commit();
  {
    uint32_t sb = shm + 24576;
    cpa_tile(sb,         Kh_p + (long long)j0t * 8192, 128, tid);
    cpa_tile(sb + 8192,  Kl_p + (long long)j0t * 8192, 128, tid);
    cpa_tile(sb + 16384, Vt_p + (long long)j0t * 128,  4096, tid);
    cpa_commit();
  }
  cpa_wait<1>();
  __syncthreads();
  uint32_t qa[2][4][4];
  ld_qa(shm, shm + 8192, lane, w, qa);
  __syncthreads();
  if (ntile >= 2) {  // K/V (j0t+1) -> stage0
    cpa_tile(shm,         Kh_p + (long long)(j0t + 1) * 8192, 128, tid);
    cpa_tile(shm + 8192,  Kl_p + (long long)(j0t + 1) * 8192, 128, tid);
    cpa_tile(shm + 16384, Vt_p + (long long)(j0t + 1) * 128,  4096, tid);
    cpa_commit();
  }

  float accO[8][4];
#pragma unroll
  for (int et = 0; et < 8; ++et)
    accO[et][0] = accO[et][1] = accO[et][2] = accO[et][3] = 0.f;
  float zac[2] = {0.f, 0.f}, eac[2] = {0.f, 0.f};

  const long long tile0 = (long long)(bh_ * NIT + it) * NJT;

  for (int jt = j0t; jt < j1t; ++jt) {
    const int st = 1 - ((jt - j0t) & 1);
    const uint32_t sb = shm + st * 24576;
    const uint32_t vfb = sb + 16384;
    const unsigned long long mb = g_mkbits[b * NJT + jt];
    if (jt < j1t - 1) cpa_wait<1>(); else cpa_wait<0>();
    __syncthreads();

    const int j0 = jt * BK;
    float sc[8][4];
    qk_tile(sc, qa, sb, sb + 8192, rowoff, coloff);

#pragma unroll
    for (int nt = 0; nt < 8; ++nt) {
      int c0 = nt * 8 + 2 * qc;
      int gj = j0 + c0;
      bool kv0 = ((mb >> c0) & 1ull) == 0;
      bool kv1 = ((mb >> (c0 + 1)) & 1ull) == 0;
      float s0 = sc[nt][0] * SCALE, s1 = sc[nt][1] * SCALE;
      float s2 = sc[nt][2] * SCALE, s3 = sc[nt][3] * SCALE;
      float e0 = (kv0 && gj     <= gi0) ? __expf(s0) : 0.f;
      float e1 = (kv1 && gj + 1 <= gi0) ? __expf(s1) : 0.f;
      float e2 = (kv0 && gj     <= gi1) ? __expf(s2) : 0.f;
      float e3 = (kv1 && gj + 1 <= gi1) ? __expf(s3) : 0.f;
      zac[0] += e0 + e1;           zac[1] += e2 + e3;
      eac[0] += e0 * s0 + e1 * s1; eac[1] += e2 * s2 + e3 * s3;
      sc[nt][0] = e0; sc[nt][1] = e1; sc[nt][2] = e2; sc[nt][3] = e3;
    }

    // store unnormalized e to gE (fp16, fragment-ordered, coalesced)
    {
      uint4* dst = gE + (tile0 + jt) * 4 * NTH + tid;
#pragma unroll
      for (int qo = 0; qo < 4; ++qo) {
        uint4 v;
        v.x = packh2(sc[2 * qo][0],     sc[2 * qo][1]);
        v.y = packh2(sc[2 * qo][2],     sc[2 * qo][3]);
        v.z = packh2(sc[2 * qo + 1][0], sc[2 * qo + 1][1]);
        v.w = packh2(sc[2 * qo + 1][2], sc[2 * qo + 1][3]);
        dst[qo * NTH] = v;
      }
    }

    // PV in fp16: P (C-layout) -> A operand; V fragments via ldmatrix.
#pragma unroll
    for (int kk = 0; kk < 4; ++kk) {
      const float* cA = sc[2 * kk];
      const float* cB = sc[2 * kk + 1];
      uint32_t ah[4];
      ah[0] = packh2(cA[0], cA[1]);
      ah[1] = packh2(cA[2], cA[3]);
      ah[2] = packh2(cB[0], cB[1]);
      ah[3] = packh2(cB[2], cB[3]);
#pragma unroll
      for (int ep = 0; ep < 4; ++ep) {
        uint32_t off = swz(ep * 16 + rowoff, kk * 16 + coloff);
        uint32_t vf[4];
        ldsm4(vf, vfb + off);
        mma16816f(accO[2 * ep],     ah, vf[0], vf[1]);
        mma16816f(accO[2 * ep + 1], ah, vf[2], vf[3]);
      }
    }
    __syncthreads();
    if (jt + 2 < j1t) {  // refill this stage with tile jt+2
      long long tb = (long long)(jt + 2) * 8192;
      cpa_tile(sb,         Kh_p + tb, 128, tid);
      cpa_tile(sb + 8192,  Kl_p + tb, 128, tid);
      cpa_tile(sb + 16384, Vt_p + (long long)(jt + 2) * 128, 4096, tid);
      cpa_commit();
    }
  }

  // ---- quad reduction of row stats ---------------------------------------
#pragma unroll
  for (int d = 1; d < 4; d <<= 1) {
    zac[0] += __shfl_xor_sync(0xffffffffu, zac[0], d);
    zac[1] += __shfl_xor_sync(0xffffffffu, zac[1], d);
    eac[0] += __shfl_xor_sync(0xffffffffu, eac[0], d);
    eac[1] += __shfl_xor_sync(0xffffffffu, eac[1], d);
  }

  if (is_split) {
    // write partials; combine kernel finalizes
    const int half = (j0t != 0) ? 1 : 0;
    const int slot = (bh_ * 16 + (it - 16)) * 2 + half;
    if (qc == 0) {
      gPZ[slot * 64 + w * 16 + qr]     = zac[0];
      gPZ[slot * 64 + w * 16 + qr + 8] = zac[1];
      gPE[slot * 64 + w * 16 + qr]     = eac[0];
      gPE[slot * 64 + w * 16 + qr + 8] = eac[1];
    }
    float4* base = gPO + slot * 1024;
#pragma unroll
    for (int et = 0; et < 8; ++et)
      base[et * NTH + tid] =
          make_float4(accO[et][0], accO[et][1], accO[et][2], accO[et][3]);
    return;
  }

  // ---- inline epilogue (full-range CTAs) ---------------------------------
  const int mq0 = mq[b * L_ + gi0];
  const int mq1 = mq[b * L_ + gi1];
  const float inv0 = mq0 ? 0.f : 1.f / zac[0];
  const float inv1 = mq1 ? 0.f : 1.f / zac[1];

  if (qc == 0) {
    long long eb = (b * H_ + h) * L_;
    outE[eb + gi0] = mq0 ? 0.f : (__logf(zac[0]) - eac[0] * inv0);
    outE[eb + gi1] = mq1 ? 0.f : (__logf(zac[1]) - eac[1] * inv1);
    g_invZ[eb + gi0] = inv0;
    g_invZ[eb + gi1] = inv1;
  }
#pragma unroll
  for (int et = 0; et < 8; ++et) {
    int ge = et * 8 + 2 * qc;
    float2 v0 = {accO[et][0] * inv0, accO[et][1] * inv0};
    float2 v1 = {accO[et][2] * inv1, accO[et][3] * inv1};
    *reinterpret_cast<float2*>(&outV[((b * L_ + gi0) * H_ + h) * E_ + ge]) = v0;
    *reinterpret_cast<float2*>(&outV[((b * L_ + gi1) * H_ + h) * E_ + ge]) = v1;
  }
}

// ===================== COMBINE (it >= 16 rows) ============================
__global__ void __launch_bounds__(NTH) combine_kernel(
    const int* __restrict__ mq, float* __restrict__ outV,
    float* __restrict__ outE) {
  const int bh_ = blockIdx.x >> 4;
  const int itm = blockIdx.x & 15;
  const int it = 16 + itm;
  const int h = bh_ & 7;
  const long long b = bh_ >> 3;
  const int tid = threadIdx.x, w = tid >> 5, lane = tid & 31;
  const int qr = lane >> 2, qc = lane & 3;
  const int gi0 = it * BQ + w * 16 + qr, gi1 = gi0 + 8;
  const int slot0 = (bh_ * 16 + itm) * 2, slot1 = slot0 + 1;

  const float z0 = gPZ[slot0 * 64 + w * 16 + qr] + gPZ[slot1 * 64 + w * 16 + qr];
  const float z1 = gPZ[slot0 * 64 + w * 16 + qr + 8] + gPZ[slot1 * 64 + w * 16 + qr + 8];
  const float e0 = gPE[slot0 * 64 + w * 16 + qr] + gPE[slot1 * 64 + w * 16 + qr];
  const float e1 = gPE[slot0 * 64 + w * 16 + qr + 8] + gPE[slot1 * 64 + w * 16 + qr + 8];

  const int mq0 = mq[b * L_ + gi0];
  const int mq1 = mq[b * L_ + gi1];
  const float inv0 = mq0 ? 0.f : 1.f / z0;
  const float inv1 = mq1 ? 0.f : 1.f / z1;

  if (qc == 0) {
    long long eb = (b * H_ + h) * L_;
    outE[eb + gi0] = mq0 ? 0.f : (__logf(z0) - e0 * inv0);
    outE[eb + gi1] = mq1 ? 0.f : (__logf(z1) - e1 * inv1);
    g_invZ[eb + gi0] = inv0;
    g_invZ[eb + gi1] = inv1;
  }

  const float4* p0 = gPO + slot0 * 1024;
  const float4* p1 = gPO + slot1 * 1024;
#pragma unroll
  for (int et = 0; et < 8; ++et) {
    float4 a = p0[et * NTH + tid];
    float4 c = p1[et * NTH + tid];
    int ge = et * 8 + 2 * qc;
    float2 v0 = {(a.x + c.x) * inv0, (a.y + c.y) * inv0};
    float2 v1 = {(a.z + c.z) * inv1, (a.w + c.w) * inv1};
    *reinterpret_cast<float2*>(&outV[((b * L_ + gi0) * H_ + h) * E_ + ge]) = v0;
    *reinterpret_cast<float2*>(&outV[((b * L_ + gi1) * H_ + h) * E_ + ge]) = v1;
  }
}

// ============================ PASS 2 ======================================
// Pure memory: A = gE * invZ (lower triangle) + zero fill (upper). No MMA.
__global__ void __launch_bounds__(NTH) pass2_kernel(float* __restrict__ outA) {
  const int blk = blockIdx.x;
  const int it = blk & (NIT - 1);
  const int bh_ = blk >> 5;
  const int i0 = it * BQ;
  const int tid = threadIdx.x, w = tid >> 5, lane = tid & 31;
  const int qr = lane >> 2, qc = lane & 3;
  const int gi0 = i0 + w * 16 + qr, gi1 = gi0 + 8;

  const float inv0 = g_invZ[(long long)bh_ * L_ + gi0];
  const float inv1 = g_invZ[(long long)bh_ * L_ + gi1];
  const long long aRow0 = ((long long)bh_ * L_ + gi0) * S_;
  const long long aRow1 = aRow0 + 8LL * S_;
  const long long tile0 = (long long)(bh_ * NIT + it) * NJT;

  for (int jt = 0; jt <= it; ++jt) {
    const int j0 = jt * BK;
    const uint4* src = gE + (tile0 + jt) * 4 * NTH + tid;
#pragma unroll
    for (int qo = 0; qo < 4; ++qo) {
      uint4 v = src[qo * NTH];
      int cA = j0 + (2 * qo) * 8 + 2 * qc;
      int cB = cA + 8;
      float2 fA0 = __half22float2(*reinterpret_cast<__half2*>(&v.x));
      float2 fA1 = __half22float2(*reinterpret_cast<__half2*>(&v.y));
      float2 fB0 = __half22float2(*reinterpret_cast<__half2*>(&v.z));
      float2 fB1 = __half22float2(*reinterpret_cast<__half2*>(&v.w));
      float2 pA0 = {fA0.x * inv0, fA0.y * inv0};
      float2 pA1 = {fA1.x * inv1, fA1.y * inv1};
      float2 pB0 = {fB0.x * inv0, fB0.y * inv0};
      float2 pB1 = {fB1.x * inv1, fB1.y * inv1};
      *reinterpret_cast<float2*>(&outA[aRow0 + cA]) = pA0;
      *reinterpret_cast<float2*>(&outA[aRow1 + cA]) = pA1;
      *reinterpret_cast<float2*>(&outA[aRow0 + cB]) = pB0;
      *reinterpret_cast<float2*>(&outA[aRow1 + cB]) = pB1;
    }
  }

  // zero-fill fully causal-masked tiles
  const float4 z4 = {0.f, 0.f, 0.f, 0.f};
  for (int jt = it + 1; jt < NJT; ++jt) {
    const long long aBase = ((long long)bh_ * L_ + i0) * S_ + jt * BK;
    for (int idx = tid; idx < BQ * (BK / 4); idx += NTH) {
      int row = idx >> 4;
      int c4 = (idx & 15) << 2;
      *reinterpret_cast<float4*>(&outA[aBase + (long long)row * S_ + c4]) = z4;
    }
  }
}

}  // namespace

extern "C" void kernel_launch(void* const* d_in, const int* in_sizes, int n_in,
                              void* d_out, int out_size) {
  const float* Q  = (const float*)d_in[0];
  const float* K  = (const float*)d_in[1];
  const float* Vv = (const float*)d_in[2];
  const int* mk   = (const int*)d_in[3];   // mask_miss_k (nonzero = missing)
  const int* mq   = (const int*)d_in[4];   // mask_miss_q
  float* out  = (float*)d_out;
  float* outV = out;
  float* outA = out + V_SZ;
  float* outE = out + V_SZ + A_SZ;

  conv_qk<<<2048, 256>>>(Q, K);
  conv_v<<<512, 256>>>(Vv);
  mask_bits<<<B_ * NJT, 64>>>(mk);
  pass1_kernel<<<NCTA1 * 16, NTH>>>(mq, outV, outE);     // 768 blocks, LPT order
  combine_kernel<<<256, NTH>>>(mq, outV, outE);
  pass2_kernel<<<B_ * H_ * NIT, NTH>>>(outA);            // 512 blocks
}